// round 15
// baseline (speedup 1.0000x reference)
#include <cuda_runtime.h>
#include <cuda_fp16.h>
#include <cstdint>

// ---------------------------------------------------------------------------
// RGCN layer, basis-factored, fp16 intermediates, tensor-core GEMM:
//   xh = fp16(x)                                 (one-time convert)
//   y[n,b,o]  = sum_i xh[n,i] * weight[b,i,o]    mma.sync fp16, fp32 acc
//   H[n,r,o]  = sum_b w_comp[r,b] * y[n,b,o]     half2 recombination
//   CSR by dst, warp-per-node:  out[d] = bias + sum_{e in csr[d]} H[src_e, et_e]
// GEMM is persistent: B tile resident per CTA, A double-buffered w/ prefetch.
// ---------------------------------------------------------------------------

#define MAX_NODES 100000
#define MAX_EDGES 3200000
#define IN_FEAT   128
#define OUT_FEAT  128
#define NUM_RELS  16
#define NUM_BASES 8
#define NCOL      (NUM_RELS * OUT_FEAT)    // 2048
#define NB        (NUM_BASES * OUT_FEAT)   // 1024

// Scratch (static __device__ globals: allocation-free rule)
__device__ __half   g_xh[(size_t)MAX_NODES * IN_FEAT]; // 25.6 MB
__device__ __half   g_WbT[NB * IN_FEAT];               // B^T [n][k] fp16, 256 KB
__device__ __half   g_Y[(size_t)MAX_NODES * NB];       // 204.8 MB
__device__ __half   g_H[(size_t)MAX_NODES * NCOL];     // 409.6 MB
__device__ int      g_off[MAX_NODES + 1];              // CSR offsets
__device__ int      g_cursor[MAX_NODES];
__device__ unsigned g_einfo[MAX_EDGES];                // src | (etype<<20)
__device__ int      g_idx64;

// ---------------------------------------------------------------------------
// Kernel 1: detect index dtype (int64 vs int32)
// ---------------------------------------------------------------------------
__global__ void detect_idx_kernel(const unsigned int* __restrict__ srcw, int n_edges)
{
    __shared__ int nz;
    if (threadIdx.x == 0) nz = 0;
    __syncthreads();
    int samples = n_edges < 2048 ? n_edges : 2048;
    for (int i = threadIdx.x; i < samples; i += blockDim.x)
        if (srcw[2 * i + 1] != 0u) atomicOr(&nz, 1);
    __syncthreads();
    if (threadIdx.x == 0) g_idx64 = (nz == 0) ? 1 : 0;
}

// ---------------------------------------------------------------------------
// Kernel 2a: x -> fp16 (vectorized)
// ---------------------------------------------------------------------------
__global__ void prep_xh_kernel(const float* __restrict__ x, int total4)
{
    int i = blockIdx.x * blockDim.x + threadIdx.x;
    if (i >= total4) return;
    float4 v = ((const float4*)x)[i];
    __half2 lo = __floats2half2_rn(v.x, v.y);
    __half2 hi = __floats2half2_rn(v.z, v.w);
    ((uint2*)g_xh)[i] = make_uint2(*(uint32_t*)&lo, *(uint32_t*)&hi);
}

// ---------------------------------------------------------------------------
// Kernel 2b: WbT[n=b*128+o][k] = (half)weight[b,k,o]
// ---------------------------------------------------------------------------
__global__ void prep_WbT_kernel(const float* __restrict__ weight)
{
    int idx = blockIdx.x * blockDim.x + threadIdx.x;
    if (idx >= NB * IN_FEAT) return;
    int n = idx >> 7;
    int k = idx & 127;
    int b = n >> 7;
    int o = n & 127;
    g_WbT[idx] = __float2half_rn(weight[((b * IN_FEAT) + k) * OUT_FEAT + o]);
}

// ---------------------------------------------------------------------------
// Kernel 3: persistent tensor-core GEMM  Y[M x 1024] = xh[M x 128] @ WbT^T
// mma.sync.m16n8k16. CTA tile 128x256, 8 warps (2m x 4n), warp tile 64x64.
// grid (4, 148): B tile loaded once per CTA; A double-buffered with register
// prefetch overlapping the mainloop. Epilogue stages 64 rows at a time
// through the dead A buffer (banks 4g+tg conflict-free), 512B coalesced STG.
// ---------------------------------------------------------------------------
#define AST 68
#define BST 68
#define SST 132
#define GM_SMEM_WORDS (256 * BST + 2 * 128 * AST)      // 34816 words
#define GM_SMEM_BYTES (GM_SMEM_WORDS * 4)              // 139264
#define GRID_Y 148

__device__ __forceinline__ void mma16816(float* d, const uint32_t* a, const uint32_t* b)
{
    asm volatile(
        "mma.sync.aligned.m16n8k16.row.col.f32.f16.f16.f32 "
        "{%0,%1,%2,%3}, {%4,%5,%6,%7}, {%8,%9}, {%0,%1,%2,%3};"
        : "+f"(d[0]), "+f"(d[1]), "+f"(d[2]), "+f"(d[3])
        : "r"(a[0]), "r"(a[1]), "r"(a[2]), "r"(a[3]), "r"(b[0]), "r"(b[1]));
}

__global__ __launch_bounds__(256, 1) void hgemm_y_kernel(int M)
{
    extern __shared__ uint32_t sh[];
    uint32_t* Bw = sh;                       // 256 * BST
    uint32_t* Abuf[2] = { sh + 256 * BST, sh + 256 * BST + 128 * AST };

    const int tid = threadIdx.x;
    const int colBase = blockIdx.x * 256;
    const int nblk = (M + 127) >> 7;

    const int ar = tid >> 1;                 // A row 0..127
    const int ah_sel = tid & 1;              // k-half

    // --- load B tile once (256 n-rows x 128 k fp16), 16 uint4 per thread ---
    {
        const uint4* src = (const uint4*)(g_WbT + (size_t)(colBase + tid) * IN_FEAT);
#pragma unroll
        for (int j = 0; j < 16; j++)
            *(uint4*)(Bw + tid * BST + j * 4) = src[j];
    }
    // --- load first A tile into buf 0 ---
    {
        int rb0 = blockIdx.y;
        if (rb0 < nblk) {
            int row = rb0 * 128 + ar;
            bool ok = row < M;
            const uint4* src = (const uint4*)(g_xh + (size_t)row * IN_FEAT + ah_sel * 64);
            uint32_t* dstw = Abuf[0] + ar * AST + ah_sel * 32;
#pragma unroll
            for (int j = 0; j < 8; j++) {
                uint4 v = make_uint4(0u, 0u, 0u, 0u);
                if (ok) v = src[j];
                *(uint4*)(dstw + j * 4) = v;
            }
        }
    }
    __syncthreads();

    const int lane = tid & 31;
    const int warp = tid >> 5;
    const int wm = warp & 1;            // 0..1
    const int wn = warp >> 1;           // 0..3
    const int g  = lane >> 2;           // 0..7
    const int tg = lane & 3;            // 0..3

    int p = 0;
    for (int rb = blockIdx.y; rb < nblk; rb += GRID_Y, p ^= 1) {
        uint32_t* Ah = Abuf[p];
        uint32_t* An = Abuf[p ^ 1];
        const int rowBase = rb * 128;
        const int rbn = rb + GRID_Y;

        // --- prefetch next A tile into registers (overlaps mainloop) ---
        uint4 pf[8];
        {
            int rown = rbn * 128 + ar;
            bool okn = (rbn < nblk) && (rown < M);
            const uint4* src = (const uint4*)(g_xh + (size_t)rown * IN_FEAT + ah_sel * 64);
#pragma unroll
            for (int j = 0; j < 8; j++)
                pf[j] = okn ? src[j] : make_uint4(0u, 0u, 0u, 0u);
        }

        // --- mainloop ---
        float acc[4][8][4];
#pragma unroll
        for (int i = 0; i < 4; i++)
#pragma unroll
            for (int j = 0; j < 8; j++)
#pragma unroll
                for (int c = 0; c < 4; c++) acc[i][j][c] = 0.f;

#pragma unroll
        for (int ks = 0; ks < 8; ks++) {
            const int kw = ks * 8;
            uint32_t bf[8][2];
#pragma unroll
            for (int nA = 0; nA < 8; nA++) {
                int n = wn * 64 + nA * 8 + g;
                bf[nA][0] = Bw[n * BST + kw + tg];
                bf[nA][1] = Bw[n * BST + kw + 4 + tg];
            }
#pragma unroll
            for (int mA = 0; mA < 4; mA++) {
                int r = wm * 64 + mA * 16 + g;
                uint32_t ahf[4];
                ahf[0] = Ah[r * AST + kw + tg];
                ahf[1] = Ah[(r + 8) * AST + kw + tg];
                ahf[2] = Ah[r * AST + kw + 4 + tg];
                ahf[3] = Ah[(r + 8) * AST + kw + 4 + tg];
#pragma unroll
                for (int nA = 0; nA < 8; nA++)
                    mma16816(acc[mA][nA], ahf, bf[nA]);
            }
        }

        // --- store prefetched A into the other buffer ---
        {
            uint32_t* dstw = An + ar * AST + ah_sel * 32;
#pragma unroll
            for (int j = 0; j < 8; j++)
                *(uint4*)(dstw + j * 4) = pf[j];
        }
        __syncthreads();     // mainloop reads of Ah done; An writes done

        // --- epilogue: two 64-row passes staged through the dead Ah buffer ---
        uint32_t* St = Ah;   // 64 rows x SST(132) = 8448 words <= 8704
#pragma unroll
        for (int pass = 0; pass < 2; pass++) {
            if (wm == pass) {
#pragma unroll
                for (int mA = 0; mA < 4; mA++) {
                    int lr = mA * 16 + g;      // local row 0..63 (wm*64 removed)
#pragma unroll
                    for (int nA = 0; nA < 8; nA++) {
                        int c2 = wn * 32 + nA * 4 + tg;
                        __half2 v0 = __floats2half2_rn(acc[mA][nA][0], acc[mA][nA][1]);
                        __half2 v1 = __floats2half2_rn(acc[mA][nA][2], acc[mA][nA][3]);
                        St[lr * SST + c2]       = *(uint32_t*)&v0;
                        St[(lr + 8) * SST + c2] = *(uint32_t*)&v1;
                    }
                }
            }
            __syncthreads();
            // read-out: warp w rows pass*64 + w*8 .. +7; lane -> uint4 of row
#pragma unroll
            for (int jj = 0; jj < 8; jj++) {
                int lr = warp * 8 + jj;
                int r  = pass * 64 + lr;
                if (rowBase + r < M)
                    ((uint4*)(g_Y + (size_t)(rowBase + r) * NB + colBase))[lane] =
                        *(const uint4*)(St + lr * SST + lane * 4);
            }
            __syncthreads();
        }
    }
}

// ---------------------------------------------------------------------------
// Kernel 4: half2 recombination  H[n, r, o2] = sum_b wc[r,b] * Y[n, b, o2]
// ---------------------------------------------------------------------------
__global__ __launch_bounds__(256) void recomb_kernel(const float* __restrict__ w_comp,
                                                     int M)
{
    __shared__ float wc[NUM_RELS * NUM_BASES];
    if (threadIdx.x < NUM_RELS * NUM_BASES)
        wc[threadIdx.x] = w_comp[threadIdx.x];
    __syncthreads();

    int node = blockIdx.x * 4 + (threadIdx.x >> 6);
    int op   = threadIdx.x & 63;
    if (node >= M) return;

    const __half2* y = (const __half2*)(g_Y + (size_t)node * NB) + op;
    float2 yv[NUM_BASES];
#pragma unroll
    for (int b = 0; b < NUM_BASES; b++)
        yv[b] = __half22float2(y[b * 64]);

    __half2* h = (__half2*)(g_H + (size_t)node * NCOL) + op;
#pragma unroll
    for (int r = 0; r < NUM_RELS; r++) {
        float sx = 0.f, sy = 0.f;
#pragma unroll
        for (int b = 0; b < NUM_BASES; b++) {
            float w = wc[r * NUM_BASES + b];
            sx += w * yv[b].x;
            sy += w * yv[b].y;
        }
        h[r * 64] = __floats2half2_rn(sx, sy);
    }
}

// ---------------------------------------------------------------------------
// CSR build: zero -> histogram -> single-CTA chunked scan -> fill
// ---------------------------------------------------------------------------
__global__ void zero_deg_kernel(int n_nodes)
{
    for (int i = blockIdx.x * blockDim.x + threadIdx.x; i <= n_nodes;
         i += gridDim.x * blockDim.x)
        g_off[i] = 0;
}

__global__ void hist_kernel(const void* __restrict__ dstp, int n_edges)
{
    for (int e = blockIdx.x * blockDim.x + threadIdx.x; e < n_edges;
         e += gridDim.x * blockDim.x) {
        int d = g_idx64 ? (int)((const long long*)dstp)[e] : ((const int*)dstp)[e];
        atomicAdd(&g_off[d], 1);
    }
}

__global__ __launch_bounds__(1024) void scan_kernel(int n_nodes)
{
    __shared__ int ps[1024];
    const int t = threadIdx.x;
    const int C = (n_nodes + 1023) / 1024;
    const int beg = t * C;
    const int end = min(beg + C, n_nodes);

    int sum = 0;
    for (int i = beg; i < end; i++) sum += g_off[i];
    ps[t] = sum;
    __syncthreads();

    for (int s = 1; s < 1024; s <<= 1) {
        int v = (t >= s) ? ps[t - s] : 0;
        __syncthreads();
        ps[t] += v;
        __syncthreads();
    }

    int run = (t == 0) ? 0 : ps[t - 1];
    for (int i = beg; i < end; i++) {
        int dgi = g_off[i];
        g_off[i] = run;
        g_cursor[i] = run;
        run += dgi;
    }
    if (t == 0) g_off[n_nodes] = ps[1023];
}

__global__ void fill_kernel(const void* __restrict__ srcp,
                            const void* __restrict__ dstp,
                            const void* __restrict__ etp, int n_edges)
{
    for (int e = blockIdx.x * blockDim.x + threadIdx.x; e < n_edges;
         e += gridDim.x * blockDim.x) {
        int s, d, t;
        if (g_idx64) {
            s = (int)((const long long*)srcp)[e];
            d = (int)((const long long*)dstp)[e];
            t = (int)((const long long*)etp)[e];
        } else {
            s = ((const int*)srcp)[e];
            d = ((const int*)dstp)[e];
            t = ((const int*)etp)[e];
        }
        int p = atomicAdd(&g_cursor[d], 1);
        g_einfo[p] = (unsigned)s | ((unsigned)t << 20);
    }
}

// ---------------------------------------------------------------------------
// Kernel 5: warp-per-destination aggregation, half-warp per edge (uint4),
// 8 edges in flight per warp iteration, shfl-combined at the end.
// ---------------------------------------------------------------------------
__device__ __forceinline__ const uint4* hrow4(unsigned ei, int hl)
{
    size_t off = ((size_t)(ei & 0xFFFFFu) * NUM_RELS + (ei >> 20)) * OUT_FEAT;
    return (const uint4*)(g_H + off) + hl;
}

__device__ __forceinline__ void acc8(float* a, uint4 v)
{
    float2 p;
    p = __half22float2(*(const __half2*)&v.x); a[0] += p.x; a[1] += p.y;
    p = __half22float2(*(const __half2*)&v.y); a[2] += p.x; a[3] += p.y;
    p = __half22float2(*(const __half2*)&v.z); a[4] += p.x; a[5] += p.y;
    p = __half22float2(*(const __half2*)&v.w); a[6] += p.x; a[7] += p.y;
}

__global__ __launch_bounds__(256) void aggregate_kernel(
    const float* __restrict__ bias, float* __restrict__ out, int M)
{
    int node = (blockIdx.x * 256 + threadIdx.x) >> 5;
    int lane = threadIdx.x & 31;
    if (node >= M) return;

    const int hl   = lane & 15;     // uint4 index within the 256B row
    const int side = lane >> 4;     // which edge of an interleaved pair

    const int beg = g_off[node];
    const int end = g_off[node + 1];

    float a[8];
#pragma unroll
    for (int k = 0; k < 8; k++) a[k] = 0.f;

    int i = beg;
    for (; i + 8 <= end; i += 8) {
        unsigned e0 = __ldg(&g_einfo[i + 0 + side]);
        unsigned e1 = __ldg(&g_einfo[i + 2 + side]);
        unsigned e2 = __ldg(&g_einfo[i + 4 + side]);
        unsigned e3 = __ldg(&g_einfo[i + 6 + side]);
        uint4 v0 = __ldg(hrow4(e0, hl));
        uint4 v1 = __ldg(hrow4(e1, hl));
        uint4 v2 = __ldg(hrow4(e2, hl));
        uint4 v3 = __ldg(hrow4(e3, hl));
        acc8(a, v0); acc8(a, v1); acc8(a, v2); acc8(a, v3);
    }
    for (; i + 2 <= end; i += 2) {
        unsigned e = __ldg(&g_einfo[i + side]);
        acc8(a, __ldg(hrow4(e, hl)));
    }
    if (i < end && side == 0) {
        unsigned e = __ldg(&g_einfo[i]);
        acc8(a, __ldg(hrow4(e, hl)));
    }

#pragma unroll
    for (int k = 0; k < 8; k++)
        a[k] += __shfl_xor_sync(0xFFFFFFFFu, a[k], 16);

    if (side == 0) {
        const float4 b0 = __ldg((const float4*)bias + hl * 2);
        const float4 b1 = __ldg((const float4*)bias + hl * 2 + 1);
        float* o = out + (size_t)node * OUT_FEAT + hl * 8;
        *(float4*)(o)     = make_float4(a[0] + b0.x, a[1] + b0.y, a[2] + b0.z, a[3] + b0.w);
        *(float4*)(o + 4) = make_float4(a[4] + b1.x, a[5] + b1.y, a[6] + b1.z, a[7] + b1.w);
    }
}

// ---------------------------------------------------------------------------
// launch.  Inputs: 0:x 1:weight 2:w_comp 3:h_bias 4:src 5:dst 6:etypes
// ---------------------------------------------------------------------------
extern "C" void kernel_launch(void* const* d_in, const int* in_sizes, int n_in,
                              void* d_out, int out_size)
{
    const float* x      = (const float*)d_in[0];
    const float* weight = (const float*)d_in[1];
    const float* w_comp = (const float*)d_in[2];
    const float* bias   = (const float*)d_in[3];
    const void*  src    = d_in[4];
    const void*  dst    = d_in[5];
    const void*  et     = d_in[6];
    float* out          = (float*)d_out;

    int n_nodes = in_sizes[0] / IN_FEAT;
    int n_edges = in_sizes[4];

    cudaFuncSetAttribute(hgemm_y_kernel,
                         cudaFuncAttributeMaxDynamicSharedMemorySize, GM_SMEM_BYTES);

    detect_idx_kernel<<<1, 256>>>((const unsigned int*)src, n_edges);
    prep_xh_kernel<<<(n_nodes * IN_FEAT / 4 + 255) / 256, 256>>>(x, n_nodes * IN_FEAT / 4);
    prep_WbT_kernel<<<(NB * IN_FEAT + 255) / 256, 256>>>(weight);

    // GEMM  Y = xh @ WbT^T  (persistent tensor-core kernel)
    {
        dim3 grid(NB / 256, GRID_Y);   // 4 x 148 = 592 CTAs, 4 exact waves
        hgemm_y_kernel<<<grid, 256, GM_SMEM_BYTES>>>(n_nodes);
    }

    // CSR build
    zero_deg_kernel<<<128, 256>>>(n_nodes);
    hist_kernel<<<2048, 256>>>(dst, n_edges);
    scan_kernel<<<1, 1024>>>(n_nodes);
    fill_kernel<<<2048, 256>>>(src, dst, et, n_edges);

    // H = recombine(Y)
    recomb_kernel<<<(n_nodes + 3) / 4, 256>>>(w_comp, n_nodes);

    // out = bias + CSR-aggregated messages
    aggregate_kernel<<<(n_nodes * 32 + 255) / 256, 256>>>(bias, out, n_nodes);
}

// round 16
// speedup vs baseline: 1.2699x; 1.2699x over previous
#include <cuda_runtime.h>
#include <cuda_fp16.h>
#include <cstdint>

// ---------------------------------------------------------------------------
// RGCN layer, basis-factored, fp16 intermediates, tensor-core GEMM:
//   xh = fp16(x)                                 (one-time convert)
//   y[n,b,o]  = sum_i xh[n,i] * weight[b,i,o]    mma.sync fp16, fp32 acc
//   H[n,r,o]  = sum_b w_comp[r,b] * y[n,b,o]     half2 recombination
//   CSR by dst, warp-per-node:  out[d] = bias + sum_{e in csr[d]} H[src_e, et_e]
// CSR build forked onto a second stream, overlapping GEMM+recomb.
// ---------------------------------------------------------------------------

#define MAX_NODES 100000
#define MAX_EDGES 3200000
#define IN_FEAT   128
#define OUT_FEAT  128
#define NUM_RELS  16
#define NUM_BASES 8
#define NCOL      (NUM_RELS * OUT_FEAT)    // 2048
#define NB        (NUM_BASES * OUT_FEAT)   // 1024

// Scratch (static __device__ globals: allocation-free rule)
__device__ __half   g_xh[(size_t)MAX_NODES * IN_FEAT]; // 25.6 MB
__device__ __half   g_WbT[NB * IN_FEAT];               // B^T [n][k] fp16, 256 KB
__device__ __half   g_Y[(size_t)MAX_NODES * NB];       // 204.8 MB
__device__ __half   g_H[(size_t)MAX_NODES * NCOL];     // 409.6 MB
__device__ int      g_off[MAX_NODES + 1];              // CSR offsets
__device__ int      g_cursor[MAX_NODES];
__device__ unsigned g_einfo[MAX_EDGES];                // src | (etype<<20)
__device__ int      g_idx64;

// ---------------------------------------------------------------------------
// Kernel 1: detect index dtype (int64 vs int32)
// ---------------------------------------------------------------------------
__global__ void detect_idx_kernel(const unsigned int* __restrict__ srcw, int n_edges)
{
    __shared__ int nz;
    if (threadIdx.x == 0) nz = 0;
    __syncthreads();
    int samples = n_edges < 2048 ? n_edges : 2048;
    for (int i = threadIdx.x; i < samples; i += blockDim.x)
        if (srcw[2 * i + 1] != 0u) atomicOr(&nz, 1);
    __syncthreads();
    if (threadIdx.x == 0) g_idx64 = (nz == 0) ? 1 : 0;
}

// ---------------------------------------------------------------------------
// Kernel 2a: x -> fp16 (vectorized)
// ---------------------------------------------------------------------------
__global__ void prep_xh_kernel(const float* __restrict__ x, int total4)
{
    int i = blockIdx.x * blockDim.x + threadIdx.x;
    if (i >= total4) return;
    float4 v = ((const float4*)x)[i];
    __half2 lo = __floats2half2_rn(v.x, v.y);
    __half2 hi = __floats2half2_rn(v.z, v.w);
    ((uint2*)g_xh)[i] = make_uint2(*(uint32_t*)&lo, *(uint32_t*)&hi);
}

// ---------------------------------------------------------------------------
// Kernel 2b: WbT[n=b*128+o][k] = (half)weight[b,k,o]
// ---------------------------------------------------------------------------
__global__ void prep_WbT_kernel(const float* __restrict__ weight)
{
    int idx = blockIdx.x * blockDim.x + threadIdx.x;
    if (idx >= NB * IN_FEAT) return;
    int n = idx >> 7;
    int k = idx & 127;
    int b = n >> 7;
    int o = n & 127;
    g_WbT[idx] = __float2half_rn(weight[((b * IN_FEAT) + k) * OUT_FEAT + o]);
}

// ---------------------------------------------------------------------------
// Kernel 3: tensor-core GEMM  Y[M x 1024] = xh[M x 128] @ WbT^T
// mma.sync.m16n8k16.f32.f16.f16.f32.  CTA tile 128x256, 8 warps (2m x 4n),
// warp tile 64x64, K=128 single shot.  (R12/R14 config: best measured, 174us.)
// Epilogue staged through SMEM: STS banks 4g+tg (conflict-free), 512B STG.
// ---------------------------------------------------------------------------
#define AST 68
#define BST 68
#define SST 132
#define GM_SMEM_WORDS (128 * AST + 256 * BST)          // 26112 (staging 128*132=16896 fits)
#define GM_SMEM_BYTES (GM_SMEM_WORDS * 4)              // 104448

__device__ __forceinline__ void mma16816(float* d, const uint32_t* a, const uint32_t* b)
{
    asm volatile(
        "mma.sync.aligned.m16n8k16.row.col.f32.f16.f16.f32 "
        "{%0,%1,%2,%3}, {%4,%5,%6,%7}, {%8,%9}, {%0,%1,%2,%3};"
        : "+f"(d[0]), "+f"(d[1]), "+f"(d[2]), "+f"(d[3])
        : "r"(a[0]), "r"(a[1]), "r"(a[2]), "r"(a[3]), "r"(b[0]), "r"(b[1]));
}

__global__ __launch_bounds__(256, 1) void hgemm_y_kernel(int M)
{
    extern __shared__ uint32_t sh[];
    uint32_t* Ah = sh;
    uint32_t* Bw = sh + 128 * AST;

    const int tid = threadIdx.x;
    const int rowBase = blockIdx.y * 128;
    const int colBase = blockIdx.x * 256;

    // --- load A tile (128x128 fp16), 8 uint4 per thread ---
    {
        int r = tid >> 1;
        int half_sel = tid & 1;             // which 64-half chunk of the row
        bool ok = (rowBase + r) < M;
        const uint4* src = (const uint4*)(g_xh + (size_t)(rowBase + r) * IN_FEAT
                                          + half_sel * 64);
        uint32_t* dstw = Ah + r * AST + half_sel * 32;
#pragma unroll
        for (int j = 0; j < 8; j++) {
            uint4 v = make_uint4(0u, 0u, 0u, 0u);
            if (ok) v = src[j];
            *(uint4*)(dstw + j * 4) = v;
        }
    }
    // --- load B tile (256 n-rows x 128 k fp16), 16 uint4 per thread ---
    {
        const uint4* src = (const uint4*)(g_WbT + (size_t)(colBase + tid) * IN_FEAT);
#pragma unroll
        for (int j = 0; j < 16; j++)
            *(uint4*)(Bw + tid * BST + j * 4) = src[j];
    }
    __syncthreads();

    const int lane = tid & 31;
    const int warp = tid >> 5;
    const int wm = warp & 1;            // 0..1
    const int wn = warp >> 1;           // 0..3
    const int g  = lane >> 2;           // 0..7
    const int tg = lane & 3;            // 0..3

    float acc[4][8][4];
#pragma unroll
    for (int i = 0; i < 4; i++)
#pragma unroll
        for (int j = 0; j < 8; j++)
#pragma unroll
            for (int c = 0; c < 4; c++) acc[i][j][c] = 0.f;

#pragma unroll
    for (int ks = 0; ks < 8; ks++) {
        const int kw = ks * 8;
        uint32_t bf[8][2];
#pragma unroll
        for (int nA = 0; nA < 8; nA++) {
            int n = wn * 64 + nA * 8 + g;
            bf[nA][0] = Bw[n * BST + kw + tg];
            bf[nA][1] = Bw[n * BST + kw + 4 + tg];
        }
#pragma unroll
        for (int mA = 0; mA < 4; mA++) {
            int r = wm * 64 + mA * 16 + g;
            uint32_t ah[4];
            ah[0] = Ah[r * AST + kw + tg];
            ah[1] = Ah[(r + 8) * AST + kw + tg];
            ah[2] = Ah[r * AST + kw + 4 + tg];
            ah[3] = Ah[(r + 8) * AST + kw + 4 + tg];
#pragma unroll
            for (int nA = 0; nA < 8; nA++)
                mma16816(acc[mA][nA], ah, bf[nA]);
        }
    }

    // --- epilogue: stage fp16 results in SMEM, then coalesced 512B row stores ---
    __syncthreads();                    // A/B consumed; reuse smem as staging
    uint32_t* St = sh;                  // [128 rows][SST u32], data cols 0..127 (half2)
#pragma unroll
    for (int mA = 0; mA < 4; mA++) {
        int r = wm * 64 + mA * 16 + g;
#pragma unroll
        for (int nA = 0; nA < 8; nA++) {
            int c2 = wn * 32 + nA * 4 + tg;   // half2 column 0..127
            __half2 v0 = __floats2half2_rn(acc[mA][nA][0], acc[mA][nA][1]);
            __half2 v1 = __floats2half2_rn(acc[mA][nA][2], acc[mA][nA][3]);
            St[r * SST + c2]       = *(uint32_t*)&v0;   // banks 4g+tg: conflict-free
            St[(r + 8) * SST + c2] = *(uint32_t*)&v1;
        }
    }
    __syncthreads();
    {
        // warp w handles rows 16w..16w+15; lane l stores uint4 l of the row:
        // one STG instruction = 32 lanes x 16B = 512B contiguous.
#pragma unroll
        for (int jj = 0; jj < 16; jj++) {
            int r = warp * 16 + jj;
            if (rowBase + r < M)
                ((uint4*)(g_Y + (size_t)(rowBase + r) * NB + colBase))[lane] =
                    *(const uint4*)(St + r * SST + lane * 4);
        }
    }
}

// ---------------------------------------------------------------------------
// Kernel 4: half2 recombination  H[n, r, o2] = sum_b wc[r,b] * Y[n, b, o2]
// ---------------------------------------------------------------------------
__global__ __launch_bounds__(256) void recomb_kernel(const float* __restrict__ w_comp,
                                                     int M)
{
    __shared__ float wc[NUM_RELS * NUM_BASES];
    if (threadIdx.x < NUM_RELS * NUM_BASES)
        wc[threadIdx.x] = w_comp[threadIdx.x];
    __syncthreads();

    int node = blockIdx.x * 4 + (threadIdx.x >> 6);
    int op   = threadIdx.x & 63;
    if (node >= M) return;

    const __half2* y = (const __half2*)(g_Y + (size_t)node * NB) + op;
    float2 yv[NUM_BASES];
#pragma unroll
    for (int b = 0; b < NUM_BASES; b++)
        yv[b] = __half22float2(y[b * 64]);

    __half2* h = (__half2*)(g_H + (size_t)node * NCOL) + op;
#pragma unroll
    for (int r = 0; r < NUM_RELS; r++) {
        float sx = 0.f, sy = 0.f;
#pragma unroll
        for (int b = 0; b < NUM_BASES; b++) {
            float w = wc[r * NUM_BASES + b];
            sx += w * yv[b].x;
            sy += w * yv[b].y;
        }
        h[r * 64] = __floats2half2_rn(sx, sy);
    }
}

// ---------------------------------------------------------------------------
// CSR build: zero -> histogram -> single-CTA chunked scan -> fill
// ---------------------------------------------------------------------------
__global__ void zero_deg_kernel(int n_nodes)
{
    for (int i = blockIdx.x * blockDim.x + threadIdx.x; i <= n_nodes;
         i += gridDim.x * blockDim.x)
        g_off[i] = 0;
}

__global__ void hist_kernel(const void* __restrict__ dstp, int n_edges)
{
    for (int e = blockIdx.x * blockDim.x + threadIdx.x; e < n_edges;
         e += gridDim.x * blockDim.x) {
        int d = g_idx64 ? (int)((const long long*)dstp)[e] : ((const int*)dstp)[e];
        atomicAdd(&g_off[d], 1);
    }
}

__global__ __launch_bounds__(1024) void scan_kernel(int n_nodes)
{
    __shared__ int ps[1024];
    const int t = threadIdx.x;
    const int C = (n_nodes + 1023) / 1024;
    const int beg = t * C;
    const int end = min(beg + C, n_nodes);

    int sum = 0;
    for (int i = beg; i < end; i++) sum += g_off[i];
    ps[t] = sum;
    __syncthreads();

    for (int s = 1; s < 1024; s <<= 1) {
        int v = (t >= s) ? ps[t - s] : 0;
        __syncthreads();
        ps[t] += v;
        __syncthreads();
    }

    int run = (t == 0) ? 0 : ps[t - 1];
    for (int i = beg; i < end; i++) {
        int dgi = g_off[i];
        g_off[i] = run;
        g_cursor[i] = run;
        run += dgi;
    }
    if (t == 0) g_off[n_nodes] = ps[1023];
}

__global__ void fill_kernel(const void* __restrict__ srcp,
                            const void* __restrict__ dstp,
                            const void* __restrict__ etp, int n_edges)
{
    for (int e = blockIdx.x * blockDim.x + threadIdx.x; e < n_edges;
         e += gridDim.x * blockDim.x) {
        int s, d, t;
        if (g_idx64) {
            s = (int)((const long long*)srcp)[e];
            d = (int)((const long long*)dstp)[e];
            t = (int)((const long long*)etp)[e];
        } else {
            s = ((const int*)srcp)[e];
            d = ((const int*)dstp)[e];
            t = ((const int*)etp)[e];
        }
        int p = atomicAdd(&g_cursor[d], 1);
        g_einfo[p] = (unsigned)s | ((unsigned)t << 20);
    }
}

// ---------------------------------------------------------------------------
// Kernel 5: warp-per-destination aggregation, half-warp per edge (uint4),
// 8 edges in flight per warp iteration, shfl-combined at the end.
// ---------------------------------------------------------------------------
__device__ __forceinline__ const uint4* hrow4(unsigned ei, int hl)
{
    size_t off = ((size_t)(ei & 0xFFFFFu) * NUM_RELS + (ei >> 20)) * OUT_FEAT;
    return (const uint4*)(g_H + off) + hl;
}

__device__ __forceinline__ void acc8(float* a, uint4 v)
{
    float2 p;
    p = __half22float2(*(const __half2*)&v.x); a[0] += p.x; a[1] += p.y;
    p = __half22float2(*(const __half2*)&v.y); a[2] += p.x; a[3] += p.y;
    p = __half22float2(*(const __half2*)&v.z); a[4] += p.x; a[5] += p.y;
    p = __half22float2(*(const __half2*)&v.w); a[6] += p.x; a[7] += p.y;
}

__global__ __launch_bounds__(256) void aggregate_kernel(
    const float* __restrict__ bias, float* __restrict__ out, int M)
{
    int node = (blockIdx.x * 256 + threadIdx.x) >> 5;
    int lane = threadIdx.x & 31;
    if (node >= M) return;

    const int hl   = lane & 15;     // uint4 index within the 256B row
    const int side = lane >> 4;     // which edge of an interleaved pair

    const int beg = g_off[node];
    const int end = g_off[node + 1];

    float a[8];
#pragma unroll
    for (int k = 0; k < 8; k++) a[k] = 0.f;

    int i = beg;
    for (; i + 8 <= end; i += 8) {
        unsigned e0 = __ldg(&g_einfo[i + 0 + side]);
        unsigned e1 = __ldg(&g_einfo[i + 2 + side]);
        unsigned e2 = __ldg(&g_einfo[i + 4 + side]);
        unsigned e3 = __ldg(&g_einfo[i + 6 + side]);
        uint4 v0 = __ldg(hrow4(e0, hl));
        uint4 v1 = __ldg(hrow4(e1, hl));
        uint4 v2 = __ldg(hrow4(e2, hl));
        uint4 v3 = __ldg(hrow4(e3, hl));
        acc8(a, v0); acc8(a, v1); acc8(a, v2); acc8(a, v3);
    }
    for (; i + 2 <= end; i += 2) {
        unsigned e = __ldg(&g_einfo[i + side]);
        acc8(a, __ldg(hrow4(e, hl)));
    }
    if (i < end && side == 0) {
        unsigned e = __ldg(&g_einfo[i]);
        acc8(a, __ldg(hrow4(e, hl)));
    }

#pragma unroll
    for (int k = 0; k < 8; k++)
        a[k] += __shfl_xor_sync(0xFFFFFFFFu, a[k], 16);

    if (side == 0) {
        const float4 b0 = __ldg((const float4*)bias + hl * 2);
        const float4 b1 = __ldg((const float4*)bias + hl * 2 + 1);
        float* o = out + (size_t)node * OUT_FEAT + hl * 8;
        *(float4*)(o)     = make_float4(a[0] + b0.x, a[1] + b0.y, a[2] + b0.z, a[3] + b0.w);
        *(float4*)(o + 4) = make_float4(a[4] + b1.x, a[5] + b1.y, a[6] + b1.z, a[7] + b1.w);
    }
}

// ---------------------------------------------------------------------------
// launch.  Inputs: 0:x 1:weight 2:w_comp 3:h_bias 4:src 5:dst 6:etypes
// CSR build forked to a second stream, overlapping GEMM + recomb.
// ---------------------------------------------------------------------------
extern "C" void kernel_launch(void* const* d_in, const int* in_sizes, int n_in,
                              void* d_out, int out_size)
{
    const float* x      = (const float*)d_in[0];
    const float* weight = (const float*)d_in[1];
    const float* w_comp = (const float*)d_in[2];
    const float* bias   = (const float*)d_in[3];
    const void*  src    = d_in[4];
    const void*  dst    = d_in[5];
    const void*  et     = d_in[6];
    float* out          = (float*)d_out;

    int n_nodes = in_sizes[0] / IN_FEAT;
    int n_edges = in_sizes[4];

    static cudaStream_t s2 = nullptr;
    static cudaEvent_t evFork = nullptr, evJoin = nullptr;
    if (s2 == nullptr) {
        cudaStreamCreateWithFlags(&s2, cudaStreamNonBlocking);
        cudaEventCreateWithFlags(&evFork, cudaEventDisableTiming);
        cudaEventCreateWithFlags(&evJoin, cudaEventDisableTiming);
        cudaFuncSetAttribute(hgemm_y_kernel,
                             cudaFuncAttributeMaxDynamicSharedMemorySize, GM_SMEM_BYTES);
    }

    // --- prologue on main stream ---
    detect_idx_kernel<<<1, 256>>>((const unsigned int*)src, n_edges);
    prep_xh_kernel<<<(n_nodes * IN_FEAT / 4 + 255) / 256, 256>>>(x, n_nodes * IN_FEAT / 4);
    prep_WbT_kernel<<<(NB * IN_FEAT + 255) / 256, 256>>>(weight);

    // --- fork: CSR build on s2 (depends only on detect) ---
    cudaEventRecord(evFork, 0);
    cudaStreamWaitEvent(s2, evFork, 0);
    zero_deg_kernel<<<128, 256, 0, s2>>>(n_nodes);
    hist_kernel<<<2048, 256, 0, s2>>>(dst, n_edges);
    scan_kernel<<<1, 1024, 0, s2>>>(n_nodes);
    fill_kernel<<<2048, 256, 0, s2>>>(src, dst, et, n_edges);
    cudaEventRecord(evJoin, s2);

    // --- main stream: GEMM  Y = xh @ WbT^T, then recomb ---
    {
        dim3 grid(NB / 256, (n_nodes + 127) / 128);
        hgemm_y_kernel<<<grid, 256, GM_SMEM_BYTES>>>(n_nodes);
    }
    recomb_kernel<<<(n_nodes + 3) / 4, 256>>>(w_comp, n_nodes);

    // --- join, then aggregate ---
    cudaStreamWaitEvent(0, evJoin, 0);
    aggregate_kernel<<<(n_nodes * 32 + 255) / 256, 256>>>(bias, out, n_nodes);
}

// round 17
// speedup vs baseline: 1.3129x; 1.0338x over previous
#include <cuda_runtime.h>
#include <cuda_fp16.h>
#include <cstdint>

// ---------------------------------------------------------------------------
// RGCN layer, basis-factored, fp16 intermediates, tensor-core GEMM:
//   xh = fp16(x)                                 (one-time convert)
//   y[n,b,o]  = sum_i xh[n,i] * weight[b,i,o]    mma.sync fp16, fp32 acc
//   H[n,r,o]  = sum_b w_comp[r,b] * y[n,b,o]     half2 recombination
//   CSR by dst, warp-per-node:  out[d] = bias + sum_{e in csr[d]} H[src_e, et_e]
// GEMM: 128x128 CTA tile, 4 warps (64x64 warp tile), 2 CTAs/SM for overlap.
// ---------------------------------------------------------------------------

#define MAX_NODES 100000
#define MAX_EDGES 3200000
#define IN_FEAT   128
#define OUT_FEAT  128
#define NUM_RELS  16
#define NUM_BASES 8
#define NCOL      (NUM_RELS * OUT_FEAT)    // 2048
#define NB        (NUM_BASES * OUT_FEAT)   // 1024

// Scratch (static __device__ globals: allocation-free rule)
__device__ __half   g_xh[(size_t)MAX_NODES * IN_FEAT]; // 25.6 MB
__device__ __half   g_WbT[NB * IN_FEAT];               // B^T [n][k] fp16, 256 KB
__device__ __half   g_Y[(size_t)MAX_NODES * NB];       // 204.8 MB
__device__ __half   g_H[(size_t)MAX_NODES * NCOL];     // 409.6 MB
__device__ int      g_off[MAX_NODES + 1];              // CSR offsets
__device__ int      g_cursor[MAX_NODES];
__device__ unsigned g_einfo[MAX_EDGES];                // src | (etype<<20)
__device__ int      g_idx64;

// ---------------------------------------------------------------------------
// Kernel 1: detect index dtype (int64 vs int32)
// ---------------------------------------------------------------------------
__global__ void detect_idx_kernel(const unsigned int* __restrict__ srcw, int n_edges)
{
    __shared__ int nz;
    if (threadIdx.x == 0) nz = 0;
    __syncthreads();
    int samples = n_edges < 2048 ? n_edges : 2048;
    for (int i = threadIdx.x; i < samples; i += blockDim.x)
        if (srcw[2 * i + 1] != 0u) atomicOr(&nz, 1);
    __syncthreads();
    if (threadIdx.x == 0) g_idx64 = (nz == 0) ? 1 : 0;
}

// ---------------------------------------------------------------------------
// Kernel 2a: x -> fp16 (vectorized)
// ---------------------------------------------------------------------------
__global__ void prep_xh_kernel(const float* __restrict__ x, int total4)
{
    int i = blockIdx.x * blockDim.x + threadIdx.x;
    if (i >= total4) return;
    float4 v = ((const float4*)x)[i];
    __half2 lo = __floats2half2_rn(v.x, v.y);
    __half2 hi = __floats2half2_rn(v.z, v.w);
    ((uint2*)g_xh)[i] = make_uint2(*(uint32_t*)&lo, *(uint32_t*)&hi);
}

// ---------------------------------------------------------------------------
// Kernel 2b: WbT[n=b*128+o][k] = (half)weight[b,k,o]
// ---------------------------------------------------------------------------
__global__ void prep_WbT_kernel(const float* __restrict__ weight)
{
    int idx = blockIdx.x * blockDim.x + threadIdx.x;
    if (idx >= NB * IN_FEAT) return;
    int n = idx >> 7;
    int k = idx & 127;
    int b = n >> 7;
    int o = n & 127;
    g_WbT[idx] = __float2half_rn(weight[((b * IN_FEAT) + k) * OUT_FEAT + o]);
}

// ---------------------------------------------------------------------------
// Kernel 3: tensor-core GEMM  Y[M x 1024] = xh[M x 128] @ WbT^T
// mma.sync.m16n8k16.  CTA tile 128x128, 4 warps (2m x 2n), warp tile 64x64,
// K=128 single shot, 128 threads, 2 CTAs/SM (prologue/sync mutual hiding).
// Epilogue staged through SMEM (reusing A+B region): banks 4g+tg conflict-free.
// ---------------------------------------------------------------------------
#define AST 68
#define BST 68
#define SST 68
#define GM_SMEM_WORDS (128 * AST + 128 * BST)          // 17408 words
#define GM_SMEM_BYTES (GM_SMEM_WORDS * 4)              // 69632 (staging 128*68=8704 fits)

__device__ __forceinline__ void mma16816(float* d, const uint32_t* a, const uint32_t* b)
{
    asm volatile(
        "mma.sync.aligned.m16n8k16.row.col.f32.f16.f16.f32 "
        "{%0,%1,%2,%3}, {%4,%5,%6,%7}, {%8,%9}, {%0,%1,%2,%3};"
        : "+f"(d[0]), "+f"(d[1]), "+f"(d[2]), "+f"(d[3])
        : "r"(a[0]), "r"(a[1]), "r"(a[2]), "r"(a[3]), "r"(b[0]), "r"(b[1]));
}

__global__ __launch_bounds__(128, 2) void hgemm_y_kernel(int M)
{
    extern __shared__ uint32_t sh[];
    uint32_t* Ah = sh;
    uint32_t* Bw = sh + 128 * AST;

    const int tid = threadIdx.x;
    const int rowBase = blockIdx.y * 128;
    const int colBase = blockIdx.x * 128;

    // --- load A tile (128 rows x 128 fp16): thread = row, 16 uint4 ---
    {
        bool ok = (rowBase + tid) < M;
        const uint4* src = (const uint4*)(g_xh + (size_t)(rowBase + tid) * IN_FEAT);
        uint32_t* dstw = Ah + tid * AST;
#pragma unroll
        for (int j = 0; j < 16; j++) {
            uint4 v = make_uint4(0u, 0u, 0u, 0u);
            if (ok) v = src[j];
            *(uint4*)(dstw + j * 4) = v;
        }
    }
    // --- load B tile (128 n-rows x 128 k fp16): thread = row, 16 uint4 ---
    {
        const uint4* src = (const uint4*)(g_WbT + (size_t)(colBase + tid) * IN_FEAT);
        uint32_t* dstw = Bw + tid * BST;
#pragma unroll
        for (int j = 0; j < 16; j++)
            *(uint4*)(dstw + j * 4) = src[j];
    }
    __syncthreads();

    const int lane = tid & 31;
    const int warp = tid >> 5;          // 0..3
    const int wm = warp & 1;            // 0..1 (M halves of 64)
    const int wn = warp >> 1;           // 0..1 (N halves of 64)
    const int g  = lane >> 2;           // 0..7
    const int tg = lane & 3;            // 0..3

    float acc[4][8][4];
#pragma unroll
    for (int i = 0; i < 4; i++)
#pragma unroll
        for (int j = 0; j < 8; j++)
#pragma unroll
            for (int c = 0; c < 4; c++) acc[i][j][c] = 0.f;

#pragma unroll
    for (int ks = 0; ks < 8; ks++) {
        const int kw = ks * 8;
        uint32_t bf[8][2];
#pragma unroll
        for (int nA = 0; nA < 8; nA++) {
            int n = wn * 64 + nA * 8 + g;
            bf[nA][0] = Bw[n * BST + kw + tg];
            bf[nA][1] = Bw[n * BST + kw + 4 + tg];
        }
#pragma unroll
        for (int mA = 0; mA < 4; mA++) {
            int r = wm * 64 + mA * 16 + g;
            uint32_t ah[4];
            ah[0] = Ah[r * AST + kw + tg];
            ah[1] = Ah[(r + 8) * AST + kw + tg];
            ah[2] = Ah[r * AST + kw + 4 + tg];
            ah[3] = Ah[(r + 8) * AST + kw + 4 + tg];
#pragma unroll
            for (int nA = 0; nA < 8; nA++)
                mma16816(acc[mA][nA], ah, bf[nA]);
        }
    }

    // --- epilogue: stage fp16 results in SMEM, then coalesced 256B row stores ---
    __syncthreads();                    // A/B consumed; reuse smem as staging
    uint32_t* St = sh;                  // [128 rows][SST u32], data cols 0..63 (half2)
#pragma unroll
    for (int mA = 0; mA < 4; mA++) {
        int r = wm * 64 + mA * 16 + g;
#pragma unroll
        for (int nA = 0; nA < 8; nA++) {
            int c2 = wn * 32 + nA * 4 + tg;   // half2 column 0..63
            __half2 v0 = __floats2half2_rn(acc[mA][nA][0], acc[mA][nA][1]);
            __half2 v1 = __floats2half2_rn(acc[mA][nA][2], acc[mA][nA][3]);
            St[r * SST + c2]       = *(uint32_t*)&v0;   // banks 4g+tg: conflict-free
            St[(r + 8) * SST + c2] = *(uint32_t*)&v1;
        }
    }
    __syncthreads();
    {
        // warp w handles rows 32w..32w+31: per iter 2 rows x 16 uint4 (256B/row)
#pragma unroll
        for (int jj = 0; jj < 16; jj++) {
            int r = warp * 32 + jj * 2 + (lane >> 4);
            int q = lane & 15;
            if (rowBase + r < M)
                ((uint4*)(g_Y + (size_t)(rowBase + r) * NB + colBase))[q] =
                    *(const uint4*)(St + r * SST + q * 4);
        }
    }
}

// ---------------------------------------------------------------------------
// Kernel 4: half2 recombination  H[n, r, o2] = sum_b wc[r,b] * Y[n, b, o2]
// ---------------------------------------------------------------------------
__global__ __launch_bounds__(256) void recomb_kernel(const float* __restrict__ w_comp,
                                                     int M)
{
    __shared__ float wc[NUM_RELS * NUM_BASES];
    if (threadIdx.x < NUM_RELS * NUM_BASES)
        wc[threadIdx.x] = w_comp[threadIdx.x];
    __syncthreads();

    int node = blockIdx.x * 4 + (threadIdx.x >> 6);
    int op   = threadIdx.x & 63;
    if (node >= M) return;

    const __half2* y = (const __half2*)(g_Y + (size_t)node * NB) + op;
    float2 yv[NUM_BASES];
#pragma unroll
    for (int b = 0; b < NUM_BASES; b++)
        yv[b] = __half22float2(y[b * 64]);

    __half2* h = (__half2*)(g_H + (size_t)node * NCOL) + op;
#pragma unroll
    for (int r = 0; r < NUM_RELS; r++) {
        float sx = 0.f, sy = 0.f;
#pragma unroll
        for (int b = 0; b < NUM_BASES; b++) {
            float w = wc[r * NUM_BASES + b];
            sx += w * yv[b].x;
            sy += w * yv[b].y;
        }
        h[r * 64] = __floats2half2_rn(sx, sy);
    }
}

// ---------------------------------------------------------------------------
// CSR build: zero -> histogram -> single-CTA chunked scan -> fill
// ---------------------------------------------------------------------------
__global__ void zero_deg_kernel(int n_nodes)
{
    for (int i = blockIdx.x * blockDim.x + threadIdx.x; i <= n_nodes;
         i += gridDim.x * blockDim.x)
        g_off[i] = 0;
}

__global__ void hist_kernel(const void* __restrict__ dstp, int n_edges)
{
    for (int e = blockIdx.x * blockDim.x + threadIdx.x; e < n_edges;
         e += gridDim.x * blockDim.x) {
        int d = g_idx64 ? (int)((const long long*)dstp)[e] : ((const int*)dstp)[e];
        atomicAdd(&g_off[d], 1);
    }
}

__global__ __launch_bounds__(1024) void scan_kernel(int n_nodes)
{
    __shared__ int ps[1024];
    const int t = threadIdx.x;
    const int C = (n_nodes + 1023) / 1024;
    const int beg = t * C;
    const int end = min(beg + C, n_nodes);

    int sum = 0;
    for (int i = beg; i < end; i++) sum += g_off[i];
    ps[t] = sum;
    __syncthreads();

    for (int s = 1; s < 1024; s <<= 1) {
        int v = (t >= s) ? ps[t - s] : 0;
        __syncthreads();
        ps[t] += v;
        __syncthreads();
    }

    int run = (t == 0) ? 0 : ps[t - 1];
    for (int i = beg; i < end; i++) {
        int dgi = g_off[i];
        g_off[i] = run;
        g_cursor[i] = run;
        run += dgi;
    }
    if (t == 0) g_off[n_nodes] = ps[1023];
}

__global__ void fill_kernel(const void* __restrict__ srcp,
                            const void* __restrict__ dstp,
                            const void* __restrict__ etp, int n_edges)
{
    for (int e = blockIdx.x * blockDim.x + threadIdx.x; e < n_edges;
         e += gridDim.x * blockDim.x) {
        int s, d, t;
        if (g_idx64) {
            s = (int)((const long long*)srcp)[e];
            d = (int)((const long long*)dstp)[e];
            t = (int)((const long long*)etp)[e];
        } else {
            s = ((const int*)srcp)[e];
            d = ((const int*)dstp)[e];
            t = ((const int*)etp)[e];
        }
        int p = atomicAdd(&g_cursor[d], 1);
        g_einfo[p] = (unsigned)s | ((unsigned)t << 20);
    }
}

// ---------------------------------------------------------------------------
// Kernel 5: warp-per-destination aggregation, half-warp per edge (uint4),
// 8 edges in flight per warp iteration, shfl-combined at the end.
// ---------------------------------------------------------------------------
__device__ __forceinline__ const uint4* hrow4(unsigned ei, int hl)
{
    size_t off = ((size_t)(ei & 0xFFFFFu) * NUM_RELS + (ei >> 20)) * OUT_FEAT;
    return (const uint4*)(g_H + off) + hl;
}

__device__ __forceinline__ void acc8(float* a, uint4 v)
{
    float2 p;
    p = __half22float2(*(const __half2*)&v.x); a[0] += p.x; a[1] += p.y;
    p = __half22float2(*(const __half2*)&v.y); a[2] += p.x; a[3] += p.y;
    p = __half22float2(*(const __half2*)&v.z); a[4] += p.x; a[5] += p.y;
    p = __half22float2(*(const __half2*)&v.w); a[6] += p.x; a[7] += p.y;
}

__global__ __launch_bounds__(256) void aggregate_kernel(
    const float* __restrict__ bias, float* __restrict__ out, int M)
{
    int node = (blockIdx.x * 256 + threadIdx.x) >> 5;
    int lane = threadIdx.x & 31;
    if (node >= M) return;

    const int hl   = lane & 15;     // uint4 index within the 256B row
    const int side = lane >> 4;     // which edge of an interleaved pair

    const int beg = g_off[node];
    const int end = g_off[node + 1];

    float a[8];
#pragma unroll
    for (int k = 0; k < 8; k++) a[k] = 0.f;

    int i = beg;
    for (; i + 8 <= end; i += 8) {
        unsigned e0 = __ldg(&g_einfo[i + 0 + side]);
        unsigned e1 = __ldg(&g_einfo[i + 2 + side]);
        unsigned e2 = __ldg(&g_einfo[i + 4 + side]);
        unsigned e3 = __ldg(&g_einfo[i + 6 + side]);
        uint4 v0 = __ldg(hrow4(e0, hl));
        uint4 v1 = __ldg(hrow4(e1, hl));
        uint4 v2 = __ldg(hrow4(e2, hl));
        uint4 v3 = __ldg(hrow4(e3, hl));
        acc8(a, v0); acc8(a, v1); acc8(a, v2); acc8(a, v3);
    }
    for (; i + 2 <= end; i += 2) {
        unsigned e = __ldg(&g_einfo[i + side]);
        acc8(a, __ldg(hrow4(e, hl)));
    }
    if (i < end && side == 0) {
        unsigned e = __ldg(&g_einfo[i]);
        acc8(a, __ldg(hrow4(e, hl)));
    }

#pragma unroll
    for (int k = 0; k < 8; k++)
        a[k] += __shfl_xor_sync(0xFFFFFFFFu, a[k], 16);

    if (side == 0) {
        const float4 b0 = __ldg((const float4*)bias + hl * 2);
        const float4 b1 = __ldg((const float4*)bias + hl * 2 + 1);
        float* o = out + (size_t)node * OUT_FEAT + hl * 8;
        *(float4*)(o)     = make_float4(a[0] + b0.x, a[1] + b0.y, a[2] + b0.z, a[3] + b0.w);
        *(float4*)(o + 4) = make_float4(a[4] + b1.x, a[5] + b1.y, a[6] + b1.z, a[7] + b1.w);
    }
}

// ---------------------------------------------------------------------------
// launch.  Inputs: 0:x 1:weight 2:w_comp 3:h_bias 4:src 5:dst 6:etypes
// (serial launch order — R16 fork experiment regressed and is reverted)
// ---------------------------------------------------------------------------
extern "C" void kernel_launch(void* const* d_in, const int* in_sizes, int n_in,
                              void* d_out, int out_size)
{
    const float* x      = (const float*)d_in[0];
    const float* weight = (const float*)d_in[1];
    const float* w_comp = (const float*)d_in[2];
    const float* bias   = (const float*)d_in[3];
    const void*  src    = d_in[4];
    const void*  dst    = d_in[5];
    const void*  et     = d_in[6];
    float* out          = (float*)d_out;

    int n_nodes = in_sizes[0] / IN_FEAT;
    int n_edges = in_sizes[4];

    cudaFuncSetAttribute(hgemm_y_kernel,
                         cudaFuncAttributeMaxDynamicSharedMemorySize, GM_SMEM_BYTES);

    detect_idx_kernel<<<1, 256>>>((const unsigned int*)src, n_edges);
    prep_xh_kernel<<<(n_nodes * IN_FEAT / 4 + 255) / 256, 256>>>(x, n_nodes * IN_FEAT / 4);
    prep_WbT_kernel<<<(NB * IN_FEAT + 255) / 256, 256>>>(weight);

    // GEMM  Y = xh @ WbT^T  (tensor cores, 128x128 CTAs, 2 CTAs/SM)
    {
        dim3 grid(NB / 128, (n_nodes + 127) / 128);
        hgemm_y_kernel<<<grid, 128, GM_SMEM_BYTES>>>(n_nodes);
    }

    // CSR build
    zero_deg_kernel<<<128, 256>>>(n_nodes);
    hist_kernel<<<2048, 256>>>(dst, n_edges);
    scan_kernel<<<1, 1024>>>(n_nodes);
    fill_kernel<<<2048, 256>>>(src, dst, et, n_edges);

    // H = recombine(Y)
    recomb_kernel<<<(n_nodes + 3) / 4, 256>>>(w_comp, n_nodes);

    // out = bias + CSR-aggregated messages
    aggregate_kernel<<<(n_nodes * 32 + 255) / 256, 256>>>(bias, out, n_nodes);
}